// round 1
// baseline (speedup 1.0000x reference)
#include <cuda_runtime.h>
#include <math.h>

// Problem constants (hardcoded from reference)
#define NB 32          // batch
#define NS 96          // src len == trg len
#define NE 256         // embed dim
#define NH 512         // hidden
#define G4H 2048       // 4*NH
#define NV 32000

// ---------------- scratch buffer offsets (floats) ----------------
#define OFF_EMBS 0u
#define OFF_EMBT (OFF_EMBS + 786432u)     // 32*96*256
#define OFF_XPA  (OFF_EMBT + 786432u)
#define OFF_XPB  (OFF_XPA + 6291456u)     // 32*96*2048
#define OFF_ENC1 (OFF_XPB + 6291456u)
#define OFF_ENC2 (OFF_ENC1 + 3145728u)    // 32*96*1024
#define OFF_ENCO (OFF_ENC2 + 3145728u)
#define OFF_DEC0 (OFF_ENCO + 1572864u)    // 32*96*512
#define OFF_COMB (OFF_DEC0 + 1572864u)
#define OFF_WT   (OFF_COMB + 3145728u)
#define OFF_HT   (OFF_WT + 6u*1048576u)   // 6 transposed Whh [512][2048]
#define OFF_CT   (OFF_HT + 65536u)        // 2*32*1024
#define OFF_SCRA (OFF_CT + 65536u)
#define OFF_SCRB (OFF_SCRA + 16384u)
#define OFF_DH0  (OFF_SCRB + 16384u)
#define OFF_DC0  (OFF_DH0 + 32768u)
#define OFF_DSCR (OFF_DC0 + 32768u)
#define TOTALF   (OFF_DSCR + 16384u)

__device__ float g_buf[TOTALF];

#define SMEM_STEP (32*513*4)
// attention smem: se 96*513 + sy 512 + sAttn 96 + sMask 96 + sRed 2
#define ATT_SE   0
#define ATT_SY   (96*513)
#define ATT_AT   (ATT_SY + 512)
#define ATT_MK   (ATT_AT + 96)
#define ATT_RD   (ATT_MK + 96)
#define SMEM_ATT ((ATT_RD + 2) * 4)

// ---------------- embedding gather ----------------
__global__ void embed_kernel(const int* __restrict__ seq,
                             const float* __restrict__ emb,
                             float* __restrict__ out) {
    int tok = blockIdx.x;
    int id = seq[tok];
    const float4* s = (const float4*)(emb + (size_t)id * NE);
    float4* d = (float4*)(out + (size_t)tok * NE);
    d[threadIdx.x] = s[threadIdx.x];   // 64 threads * 4 floats = 256
}

// ---------------- transpose Whh [2048,512] -> [512,2048] ----------------
__global__ void transpose_kernel(const float* __restrict__ W, float* __restrict__ WT) {
    __shared__ float tile[32][33];
    int k0 = blockIdx.x * 32, g0 = blockIdx.y * 32;
    int tx = threadIdx.x, ty = threadIdx.y;  // (32,8)
#pragma unroll
    for (int i = 0; i < 4; i++)
        tile[ty + i * 8][tx] = W[(size_t)(g0 + ty + i * 8) * NH + k0 + tx];
    __syncthreads();
#pragma unroll
    for (int i = 0; i < 4; i++)
        WT[(size_t)(k0 + ty + i * 8) * G4H + g0 + tx] = tile[tx][ty + i * 8];
}

// ---------------- generic SGEMM: C[M,N] = A[M,K] @ B[N,K]^T + bias ----------------
__global__ void __launch_bounds__(256) sgemm_kernel(
    const float* __restrict__ A, const float* __restrict__ Bw,
    const float* __restrict__ bias, float* __restrict__ C,
    int M, int N, int K) {
    __shared__ __align__(16) float As[8][128];
    __shared__ __align__(16) float Bs[8][128];
    int tid = threadIdx.x;
    int bn = blockIdx.x, bm = blockIdx.y;
    int row = tid >> 1;
    int kq = (tid & 1) * 4;
    int gm = bm * 128 + row;
    int gn = bn * 128 + row;
    int tx = tid & 15, ty = tid >> 4;
    bool am = gm < M, bv_ok = gn < N;
    const float* Aptr = A + (size_t)gm * K + kq;
    const float* Bptr = Bw + (size_t)gn * K + kq;
    float acc[8][8];
#pragma unroll
    for (int i = 0; i < 8; i++)
#pragma unroll
        for (int j = 0; j < 8; j++) acc[i][j] = 0.f;

    for (int k0 = 0; k0 < K; k0 += 8) {
        float4 av = am ? *(const float4*)(Aptr + k0) : make_float4(0, 0, 0, 0);
        float4 bv = bv_ok ? *(const float4*)(Bptr + k0) : make_float4(0, 0, 0, 0);
        __syncthreads();
        As[kq + 0][row] = av.x; As[kq + 1][row] = av.y;
        As[kq + 2][row] = av.z; As[kq + 3][row] = av.w;
        Bs[kq + 0][row] = bv.x; Bs[kq + 1][row] = bv.y;
        Bs[kq + 2][row] = bv.z; Bs[kq + 3][row] = bv.w;
        __syncthreads();
#pragma unroll
        for (int kk = 0; kk < 8; kk++) {
            float4 a0 = *(const float4*)&As[kk][ty * 8];
            float4 a1 = *(const float4*)&As[kk][ty * 8 + 4];
            float4 b0 = *(const float4*)&Bs[kk][tx * 8];
            float4 b1 = *(const float4*)&Bs[kk][tx * 8 + 4];
            float a[8] = {a0.x, a0.y, a0.z, a0.w, a1.x, a1.y, a1.z, a1.w};
            float b[8] = {b0.x, b0.y, b0.z, b0.w, b1.x, b1.y, b1.z, b1.w};
#pragma unroll
            for (int i = 0; i < 8; i++)
#pragma unroll
                for (int j = 0; j < 8; j++)
                    acc[i][j] = fmaf(a[i], b[j], acc[i][j]);
        }
    }
#pragma unroll
    for (int i = 0; i < 8; i++) {
        int m = bm * 128 + ty * 8 + i;
        if (m >= M) continue;
#pragma unroll
        for (int j = 0; j < 8; j++) {
            int n = bn * 128 + tx * 8 + j;
            if (n < N) C[(size_t)m * N + n] = acc[i][j] + bias[n];
        }
    }
}

// ---------------- LSTM step ----------------
struct StepArgs {
    const float* xp;     // [B, S, 4H]
    const float* WT;     // [512][2048]
    const float* h_in;   // [B] rows, stride h_in_stride
    float* h_out;
    float* c;
    float* hs;           // pre-offset by column; row stride hs_stride
    int t, t_out, h_in_stride, h_out_stride, c_stride, hs_stride;
};

__device__ __forceinline__ float sigm(float x) { return 1.f / (1.f + expf(-x)); }

__device__ __forceinline__ void lstm_epilogue(const StepArgs& a, int b, int col,
                                              float ai, float af, float ag, float ao) {
    int xb = (b * NS + a.t) * G4H + col;
    float gi = ai + a.xp[xb];
    float gf = af + a.xp[xb + 512];
    float gg = ag + a.xp[xb + 1024];
    float go = ao + a.xp[xb + 1536];
    float iv = sigm(gi), fv = sigm(gf), gv = tanhf(gg), ov = sigm(go);
    int ci = b * a.c_stride + col;
    float cn = fv * a.c[ci] + iv * gv;
    a.c[ci] = cn;
    float hn = ov * tanhf(cn);
    a.h_out[b * a.h_out_stride + col] = hn;
    a.hs[(b * NS + a.t_out) * a.hs_stride + col] = hn;
}

__global__ void __launch_bounds__(256) lstm_step_kernel(StepArgs a0, StepArgs a1) {
    StepArgs a = (blockIdx.y == 0) ? a0 : a1;
    extern __shared__ float sh[];  // [32][513]
    int tid = threadIdx.x;
#pragma unroll
    for (int i = 0; i < 64; i++) {           // 64*256 = 32*512
        int idx = tid + i * 256;
        int b = idx >> 9, k = idx & 511;
        sh[b * 513 + k] = a.h_in[b * a.h_in_stride + k];
    }
    __syncthreads();
    const int c16 = tid & 15;
    const int brow = tid >> 4;               // 0..15 -> batches brow, brow+16
    const int col = blockIdx.x * 16 + c16;
    const float* W = a.WT + col;
    const float* s0 = sh + brow * 513;
    const float* s1 = sh + (brow + 16) * 513;
    float ai0 = 0, af0 = 0, ag0 = 0, ao0 = 0;
    float ai1 = 0, af1 = 0, ag1 = 0, ao1 = 0;
#pragma unroll 8
    for (int k = 0; k < NH; k++) {
        const float* wk = W + k * G4H;
        float wi = __ldg(wk);
        float wf = __ldg(wk + 512);
        float wg = __ldg(wk + 1024);
        float wo = __ldg(wk + 1536);
        float h0 = s0[k], h1 = s1[k];
        ai0 = fmaf(h0, wi, ai0); af0 = fmaf(h0, wf, af0);
        ag0 = fmaf(h0, wg, ag0); ao0 = fmaf(h0, wo, ao0);
        ai1 = fmaf(h1, wi, ai1); af1 = fmaf(h1, wf, af1);
        ag1 = fmaf(h1, wg, ag1); ao1 = fmaf(h1, wo, ao1);
    }
    lstm_epilogue(a, brow, col, ai0, af0, ag0, ao0);
    lstm_epilogue(a, brow + 16, col, ai1, af1, ag1, ao1);
}

// ---------------- fused attention: energy + mask + softmax + context ----------------
__global__ void __launch_bounds__(128) attention_kernel(
    const float* __restrict__ encout,   // [B,S,512]
    const int* __restrict__ src,        // [B,S]
    float* __restrict__ comb) {         // [B,T,1024]; y in [:512], ctx written to [512:]
    extern __shared__ float sh[];
    float* se = sh + ATT_SE;
    float* sy = sh + ATT_SY;
    float* sAttn = sh + ATT_AT;
    float* sMask = sh + ATT_MK;
    float* sRed = sh + ATT_RD;
    int b = blockIdx.x;
    int tchunk = blockIdx.y;
    int tid = threadIdx.x;

    for (int i = tid; i < 96 * 128; i += 128) {
        int r = i >> 7, c4 = (i & 127) << 2;
        float4 v = *(const float4*)(encout + ((size_t)(b * NS + r)) * NH + c4);
        float* d = se + r * 513 + c4;
        d[0] = v.x; d[1] = v.y; d[2] = v.z; d[3] = v.w;
    }
    if (tid < 96) sMask[tid] = (src[b * NS + tid] != 0) ? 1.f : 0.f;
    __syncthreads();

    for (int tt = 0; tt < 8; tt++) {
        int t = tchunk * 8 + tt;
        ((float4*)sy)[tid] = *(const float4*)(comb + ((size_t)(b * NS + t)) * 1024 + tid * 4);
        __syncthreads();
        if (tid < 96) {
            float e = 0.f;
            const float* r = se + tid * 513;
#pragma unroll 8
            for (int k = 0; k < NH; k++) e = fmaf(sy[k], r[k], e);
            sAttn[tid] = (sMask[tid] != 0.f) ? e : -1e10f;
        }
        __syncthreads();
        if (tid < 32) {
            float m = fmaxf(sAttn[tid], fmaxf(sAttn[tid + 32], sAttn[tid + 64]));
            for (int o = 16; o > 0; o >>= 1) m = fmaxf(m, __shfl_xor_sync(0xffffffffu, m, o));
            if (tid == 0) sRed[0] = m;
        }
        __syncthreads();
        if (tid < 96) sAttn[tid] = expf(sAttn[tid] - sRed[0]);
        __syncthreads();
        if (tid < 32) {
            float s = sAttn[tid] + sAttn[tid + 32] + sAttn[tid + 64];
            for (int o = 16; o > 0; o >>= 1) s += __shfl_xor_sync(0xffffffffu, s, o);
            if (tid == 0) sRed[1] = s;
        }
        __syncthreads();
        float inv = 1.f / sRed[1];
        float acc0 = 0, acc1 = 0, acc2 = 0, acc3 = 0;
        for (int s = 0; s < 96; s++) {
            float w = sAttn[s];
            const float* r = se + s * 513;
            acc0 = fmaf(w, r[tid], acc0);
            acc1 = fmaf(w, r[tid + 128], acc1);
            acc2 = fmaf(w, r[tid + 256], acc2);
            acc3 = fmaf(w, r[tid + 384], acc3);
        }
        float* o = comb + ((size_t)(b * NS + t)) * 1024 + 512;
        o[tid] = acc0 * inv; o[tid + 128] = acc1 * inv;
        o[tid + 256] = acc2 * inv; o[tid + 384] = acc3 * inv;
        __syncthreads();
    }
}

// ---------------- host orchestration ----------------
extern "C" void kernel_launch(void* const* d_in, const int* in_sizes, int n_in,
                              void* d_out, int out_size) {
    const int* src_seq = (const int*)d_in[0];
    const int* trg_seq = (const int*)d_in[1];
    const float* src_emb = (const float*)d_in[2];
    const float* trg_emb = (const float*)d_in[3];
    const float* eW0f = (const float*)d_in[4];
    const float* eU0f = (const float*)d_in[5];
    const float* eb0f = (const float*)d_in[6];
    const float* eW0b = (const float*)d_in[7];
    const float* eU0b = (const float*)d_in[8];
    const float* eb0b = (const float*)d_in[9];
    const float* eW1f = (const float*)d_in[10];
    const float* eU1f = (const float*)d_in[11];
    const float* eb1f = (const float*)d_in[12];
    const float* eW1b = (const float*)d_in[13];
    const float* eU1b = (const float*)d_in[14];
    const float* eb1b = (const float*)d_in[15];
    const float* out_W = (const float*)d_in[16];
    const float* out_b = (const float*)d_in[17];
    const float* hpW = (const float*)d_in[18];
    const float* hpb = (const float*)d_in[19];
    const float* cpW = (const float*)d_in[20];
    const float* cpb = (const float*)d_in[21];
    const float* dW0 = (const float*)d_in[22];
    const float* dU0 = (const float*)d_in[23];
    const float* db0 = (const float*)d_in[24];
    const float* dW1 = (const float*)d_in[25];
    const float* dU1 = (const float*)d_in[26];
    const float* db1 = (const float*)d_in[27];
    const float* fcW = (const float*)d_in[28];
    const float* fcb = (const float*)d_in[29];
    float* out = (float*)d_out;

    float* g = nullptr;
    cudaGetSymbolAddress((void**)&g, g_buf);

    cudaFuncSetAttribute(lstm_step_kernel, cudaFuncAttributeMaxDynamicSharedMemorySize, SMEM_STEP);
    cudaFuncSetAttribute(attention_kernel, cudaFuncAttributeMaxDynamicSharedMemorySize, SMEM_ATT);

    float* embS = g + OFF_EMBS;
    float* embT = g + OFF_EMBT;
    float* xpA = g + OFF_XPA;
    float* xpB = g + OFF_XPB;
    float* enc1 = g + OFF_ENC1;
    float* enc2 = g + OFF_ENC2;
    float* enco = g + OFF_ENCO;
    float* dec0 = g + OFF_DEC0;
    float* comb = g + OFF_COMB;
    float* wt = g + OFF_WT;
    float* scrA = g + OFF_SCRA;
    float* scrB = g + OFF_SCRB;
    float* dscr = g + OFF_DSCR;

    // Transpose all 6 recurrent weight matrices
    const float* Us[6] = {eU0f, eU0b, eU1f, eU1b, dU0, dU1};
    for (int i = 0; i < 6; i++)
        transpose_kernel<<<dim3(16, 64), dim3(32, 8)>>>(Us[i], wt + (size_t)i * 1048576u);

    embed_kernel<<<NB * NS, 64>>>(src_seq, src_emb, embS);
    embed_kernel<<<NB * NS, 64>>>(trg_seq, trg_emb, embT);

    // zero encoder initial h/c states (hT+cT regions contiguous)
    cudaMemsetAsync(g + OFF_HT, 0, 131072u * sizeof(float));

    // ---------------- encoder ----------------
    for (int l = 0; l < 2; l++) {
        const float* xin = l ? enc1 : embS;
        int K = l ? 1024 : 256;
        const float* Wf = l ? eW1f : eW0f; const float* bf = l ? eb1f : eb0f;
        const float* Wb = l ? eW1b : eW0b; const float* bb = l ? eb1b : eb0b;
        sgemm_kernel<<<dim3(16, 24), 256>>>(xin, Wf, bf, xpA, NB * NS, G4H, K);
        sgemm_kernel<<<dim3(16, 24), 256>>>(xin, Wb, bb, xpB, NB * NS, G4H, K);

        float* hs = l ? enc2 : enc1;
        float* hT = g + OFF_HT + (size_t)l * 32768u;
        float* cT = g + OFF_CT + (size_t)l * 32768u;
        const float* WTf = wt + (size_t)(2 * l) * 1048576u;
        const float* WTb = wt + (size_t)(2 * l + 1) * 1048576u;
        for (int i = 0; i < 96; i++) {
            bool even = (i & 1) == 0;
            StepArgs f, r;
            f.xp = xpA; f.WT = WTf; f.t = i; f.t_out = i;
            f.h_in = even ? hT : scrA;  f.h_in_stride = even ? 1024 : 512;
            f.h_out = even ? scrA : hT; f.h_out_stride = even ? 512 : 1024;
            f.c = cT; f.c_stride = 1024;
            f.hs = hs; f.hs_stride = 1024;
            r.xp = xpB; r.WT = WTb; r.t = 95 - i; r.t_out = 95 - i;
            r.h_in = even ? hT + 512 : scrB;  r.h_in_stride = even ? 1024 : 512;
            r.h_out = even ? scrB : hT + 512; r.h_out_stride = even ? 512 : 1024;
            r.c = cT + 512; r.c_stride = 1024;
            r.hs = hs + 512; r.hs_stride = 1024;
            lstm_step_kernel<<<dim3(32, 2), 256, SMEM_STEP>>>(f, r);
        }
    }

    // enc_out = enc2 @ out_W^T + out_b
    sgemm_kernel<<<dim3(4, 24), 256>>>(enc2, out_W, out_b, enco, NB * NS, NH, 1024);

    // bridge projections h0/c0
    for (int l = 0; l < 2; l++) {
        sgemm_kernel<<<dim3(4, 1), 256>>>(g + OFF_HT + (size_t)l * 32768u,
                                          hpW + (size_t)l * 524288u, hpb + l * 512,
                                          g + OFF_DH0 + (size_t)l * 16384u, NB, NH, 1024);
        sgemm_kernel<<<dim3(4, 1), 256>>>(g + OFF_CT + (size_t)l * 32768u,
                                          cpW + (size_t)l * 524288u, cpb + l * 512,
                                          g + OFF_DC0 + (size_t)l * 16384u, NB, NH, 1024);
    }

    // ---------------- decoder ----------------
    for (int l = 0; l < 2; l++) {
        const float* xin = l ? dec0 : embT;
        int K = l ? 512 : 256;
        const float* W = l ? dW1 : dW0; const float* bi = l ? db1 : db0;
        sgemm_kernel<<<dim3(16, 24), 256>>>(xin, W, bi, xpA, NB * NS, G4H, K);

        float* h0 = g + OFF_DH0 + (size_t)l * 16384u;
        float* c0 = g + OFF_DC0 + (size_t)l * 16384u;
        const float* WTd = wt + (size_t)(4 + l) * 1048576u;
        float* hs = l ? comb : dec0;
        int hsStride = l ? 1024 : 512;
        for (int i = 0; i < 96; i++) {
            bool even = (i & 1) == 0;
            StepArgs a;
            a.xp = xpA; a.WT = WTd; a.t = i; a.t_out = i;
            a.h_in = even ? h0 : dscr; a.h_in_stride = 512;
            a.h_out = even ? dscr : h0; a.h_out_stride = 512;
            a.c = c0; a.c_stride = 512;
            a.hs = hs; a.hs_stride = hsStride;
            lstm_step_kernel<<<dim3(32, 1), 256, SMEM_STEP>>>(a, a);
        }
    }

    // attention: writes context into comb[:, 512:1024]
    attention_kernel<<<dim3(32, 12), 128, SMEM_ATT>>>(enco, src_seq, comb);

    // logits = comb @ fcW^T + fcb
    sgemm_kernel<<<dim3(250, 24), 256>>>(comb, fcW, fcb, out, NB * NS, NV, 1024);
}